// round 1
// baseline (speedup 1.0000x reference)
#include <cuda_runtime.h>
#include <math.h>
#include <stdint.h>

// Problem dims
#define NB   32      // batch
#define NTX  128     // encoder time
#define NTY  64      // decoder time
#define NV   50000   // vocab
#define ND   128     // embed dim
#define NH   256     // hidden
#define NG4  1024    // 4*H

// ---------------- scratch (device globals; no allocation allowed) ----------
__device__ float g_xz_enc[NTX * NB * NG4];   // x-part of gates + bias, encoder (16.8 MB)
__device__ float g_xz_dec[NTY * NB * NG4];   // decoder (8.4 MB)
__device__ float g_hs[NTY * NB * NH];        // decoder hidden outputs, [t][b][h]
__device__ float g_c[NB * NH];               // cell state
__device__ float g_hb[2 * NB * NH];          // double-buffered hidden state

__global__ void init_state() {
    int i = blockIdx.x * blockDim.x + threadIdx.x;
    if (i < NB * NH) {
        g_c[i] = 0.f;
        g_hb[i] = 0.f;
        g_hb[NB * NH + i] = 0.f;
    }
}

// ---------------- embedding + input premul: out[t*B+b][col] = E[tok] @ W[0:D] + bias
// M = T*B rows, N = 1024, K = 128. 64x64 tiles, 256 threads, 4x4 micro.
__global__ void __launch_bounds__(256) embed_gemm(
    const int* __restrict__ tokens, int T, int which,
    const float* __restrict__ E, const float* __restrict__ W,
    const float* __restrict__ bias)
{
    float* out = which ? g_xz_dec : g_xz_enc;
    __shared__ float As[16][65];
    __shared__ float Bs[16][64];
    __shared__ int   tok[64];

    int tid  = threadIdx.x;
    int row0 = blockIdx.y * 64;
    int col0 = blockIdx.x * 64;

    if (tid < 64) {
        int row = row0 + tid;
        int b = row & 31, t = row >> 5;
        tok[tid] = tokens[b * T + t];
    }
    __syncthreads();

    int tx = tid & 15, ty = tid >> 4;
    float acc[4][4] = {};

    for (int k0 = 0; k0 < ND; k0 += 16) {
        #pragma unroll
        for (int i = 0; i < 4; i++) {
            int idx = tid + i * 256;
            int kk = idx >> 6, m = idx & 63;
            As[kk][m] = E[(long)tok[m] * ND + k0 + kk];
            Bs[kk][m] = W[(long)(k0 + kk) * NG4 + col0 + m];
        }
        __syncthreads();
        #pragma unroll
        for (int kk = 0; kk < 16; kk++) {
            float a[4], bfr[4];
            #pragma unroll
            for (int i = 0; i < 4; i++) a[i] = As[kk][ty * 4 + i];
            #pragma unroll
            for (int j = 0; j < 4; j++) bfr[j] = Bs[kk][tx * 4 + j];
            #pragma unroll
            for (int i = 0; i < 4; i++)
                #pragma unroll
                for (int j = 0; j < 4; j++)
                    acc[i][j] += a[i] * bfr[j];
        }
        __syncthreads();
    }
    #pragma unroll
    for (int i = 0; i < 4; i++) {
        int row = row0 + ty * 4 + i;
        #pragma unroll
        for (int j = 0; j < 4; j++) {
            int col = col0 + tx * 4 + j;
            out[(long)row * NG4 + col] = acc[i][j] + bias[col];
        }
    }
}

__device__ __forceinline__ float sigm(float x) { return 1.f / (1.f + expf(-x)); }

// ---------------- one LSTM step -------------------------------------------
// Grid: 128 blocks; block bk owns hidden units {2bk, 2bk+1} for all 32 batches.
// z = xz[t] + h_in @ W[D:D+H].  pin selects the h double-buffer.
__global__ void __launch_bounds__(256) lstm_step(
    int t, int is_enc, int pin,
    const float* __restrict__ W, const int* __restrict__ len)
{
    __shared__ float hsm[NB * 257];   // padded: bank = (b + k) % 32, conflict-free
    __shared__ float zsm[256];

    const float* xz   = (is_enc ? g_xz_enc : g_xz_dec) + (long)t * NB * NG4;
    const float* hin  = g_hb + (long)pin * NB * NH;
    float*       hout = g_hb + (long)(pin ^ 1) * NB * NH;

    int tid = threadIdx.x;
    int u0  = blockIdx.x * 2;

    for (int i = tid; i < NB * NH; i += 256)
        hsm[(i >> 8) * 257 + (i & 255)] = hin[i];
    __syncthreads();

    int b    = tid & 31;
    int cidx = tid >> 5;          // 0..7 : gate g = cidx>>1, unit offset = cidx&1
    int g    = cidx >> 1, ul = cidx & 1;
    int col  = g * NH + u0 + ul;

    float acc0 = xz[b * NG4 + col], acc1 = 0.f;
    const float* wc = W + (long)ND * NG4 + col;   // warp-uniform column
    const float* hr = hsm + b * 257;
    #pragma unroll 8
    for (int k = 0; k < NH; k += 2) {
        acc0 += hr[k]     * wc[(long)k * NG4];
        acc1 += hr[k + 1] * wc[(long)(k + 1) * NG4];
    }
    zsm[cidx * 32 + b] = acc0 + acc1;
    __syncthreads();

    if (tid < 64) {
        int ul2 = tid >> 5, bb = tid & 31;
        int unit = u0 + ul2;
        float zi = zsm[(0 + ul2) * 32 + bb];
        float zj = zsm[(2 + ul2) * 32 + bb];
        float zf = zsm[(4 + ul2) * 32 + bb];
        float zo = zsm[(6 + ul2) * 32 + bb];
        int sidx = bb * NH + unit;
        float cold = g_c[sidx];
        float nc = cold * sigm(zf + 1.f) + sigm(zi) * tanhf(zj);
        float nh = tanhf(nc) * sigm(zo);
        if (is_enc && t >= len[bb]) { nc = cold; nh = hsm[bb * 257 + unit]; }
        g_c[sidx]  = nc;
        hout[sidx] = nh;
        if (!is_enc) g_hs[((long)t * NB + bb) * NH + unit] = nh;
    }
}

// ---------------- projection: logits[b][t][v] = hs[t][b][:] @ Wp[:, v] -----
// M=2048 (t*B+b), N=50000, K=256. 128x128 tile, kt=8, 8x8 micro with packed
// f32x2 FMAs (full-rate fp32 on sm_103a; scalar 3-reg FFMA is half rate).
__global__ void __launch_bounds__(256) proj_gemm(
    const float* __restrict__ Wp, float* __restrict__ out)
{
    __shared__ float As[8][128];
    __shared__ float Bs[8][128];

    int tid  = threadIdx.x;
    int col0 = blockIdx.x * 128;
    int row0 = blockIdx.y * 128;
    int tx = tid & 15, ty = tid >> 4;

    unsigned long long acc2[4][8];
    #pragma unroll
    for (int i = 0; i < 4; i++)
        #pragma unroll
        for (int j = 0; j < 8; j++) acc2[i][j] = 0ull;

    int aRow = tid >> 1, aK = (tid & 1) * 4;
    int bK   = tid >> 5, bN = (tid & 31) * 4;

    for (int k0 = 0; k0 < NH; k0 += 8) {
        float4 a4 = *reinterpret_cast<const float4*>(
            &g_hs[(long)(row0 + aRow) * NH + k0 + aK]);
        As[aK + 0][aRow] = a4.x;
        As[aK + 1][aRow] = a4.y;
        As[aK + 2][aRow] = a4.z;
        As[aK + 3][aRow] = a4.w;

        int gn = col0 + bN;
        float4 b4 = make_float4(0.f, 0.f, 0.f, 0.f);
        if (gn < NV)
            b4 = *reinterpret_cast<const float4*>(&Wp[(long)(k0 + bK) * NV + gn]);
        *reinterpret_cast<float4*>(&Bs[bK][bN]) = b4;
        __syncthreads();

        #pragma unroll
        for (int kk = 0; kk < 8; kk++) {
            const ulonglong2* ap =
                reinterpret_cast<const ulonglong2*>(&As[kk][ty * 8]);
            ulonglong2 A01 = ap[0], A23 = ap[1];
            unsigned long long a[4] = {A01.x, A01.y, A23.x, A23.y};
            float4 blo = *reinterpret_cast<const float4*>(&Bs[kk][tx * 8]);
            float4 bhi = *reinterpret_cast<const float4*>(&Bs[kk][tx * 8 + 4]);
            float bf[8] = {blo.x, blo.y, blo.z, blo.w, bhi.x, bhi.y, bhi.z, bhi.w};
            #pragma unroll
            for (int j = 0; j < 8; j++) {
                unsigned long long bbp;
                asm("mov.b64 %0, {%1, %2};" : "=l"(bbp) : "f"(bf[j]), "f"(bf[j]));
                #pragma unroll
                for (int i = 0; i < 4; i++)
                    asm("fma.rn.f32x2 %0, %1, %2, %3;"
                        : "=l"(acc2[i][j])
                        : "l"(a[i]), "l"(bbp), "l"(acc2[i][j]));
            }
        }
        __syncthreads();
    }

    #pragma unroll
    for (int i2 = 0; i2 < 4; i2++) {
        int m0 = row0 + ty * 8 + i2 * 2;
        #pragma unroll
        for (int j = 0; j < 8; j++) {
            int n = col0 + tx * 8 + j;
            if (n < NV) {
                unsigned long long v = acc2[i2][j];
                float lo = __uint_as_float((unsigned)(v & 0xffffffffull));
                float hi = __uint_as_float((unsigned)(v >> 32));
                int m = m0, tt = m >> 5, bb = m & 31;
                out[(long)bb * NTY * NV + (long)tt * NV + n] = lo;
                m = m0 + 1; tt = m >> 5; bb = m & 31;
                out[(long)bb * NTY * NV + (long)tt * NV + n] = hi;
            }
        }
    }
}

// ---------------- launch ----------------------------------------------------
extern "C" void kernel_launch(void* const* d_in, const int* in_sizes, int n_in,
                              void* d_out, int out_size)
{
    const int*   enc_in = (const int*)d_in[0];
    const int*   dec_in = (const int*)d_in[1];
    const int*   len    = (const int*)d_in[2];
    const float* E      = (const float*)d_in[3];
    const float* W_enc  = (const float*)d_in[4];
    const float* b_enc  = (const float*)d_in[5];
    const float* W_dec  = (const float*)d_in[6];
    const float* b_dec  = (const float*)d_in[7];
    const float* W_proj = (const float*)d_in[8];
    float* out = (float*)d_out;

    init_state<<<32, 256>>>();

    // x-part of all gate pre-activations (bias folded in)
    embed_gemm<<<dim3(16, (NTX * NB) / 64), 256>>>(enc_in, NTX, 0, E, W_enc, b_enc);
    embed_gemm<<<dim3(16, (NTY * NB) / 64), 256>>>(dec_in, NTY, 1, E, W_dec, b_dec);

    // recurrence (graph nodes serialize steps; h is double-buffered)
    int s = 0;
    for (int t = 0; t < NTX; t++, s++)
        lstm_step<<<128, 256>>>(t, 1, s & 1, W_enc, len);
    for (int t = 0; t < NTY; t++, s++)
        lstm_step<<<128, 256>>>(t, 0, s & 1, W_dec, nullptr);

    // output projection
    proj_gemm<<<dim3((NV + 127) / 128, (NTY * NB) / 128), 256>>>(W_proj, out);
}

// round 2
// speedup vs baseline: 1.5395x; 1.5395x over previous
#include <cuda_runtime.h>
#include <math.h>
#include <stdint.h>

// Problem dims
#define NB   32      // batch
#define NTX  128     // encoder time
#define NTY  64      // decoder time
#define NV   50000   // vocab
#define ND   128     // embed dim
#define NH   256     // hidden
#define NG4  1024    // 4*H
#define NSTEPS (NTX + NTY)
#define NBLK 128     // persistent recurrence blocks (<= SM count, single wave)

// ---------------- scratch (device globals; no allocation allowed) ----------
__device__ float g_xz_enc[NTX * NG4 * NB];   // x-part of gates + bias, [t][col][b]
__device__ float g_xz_dec[NTY * NG4 * NB];   // decoder, [t][col][b]
__device__ float g_hs[NTY * NB * NH];        // decoder hidden outputs, [t][b][h]
__device__ float g_ht[2 * NH * NB];          // double-buffered hidden, transposed [p][unit][b]
__device__ int   g_bar[NBLK * 32];           // grid-barrier epoch flags, 128B apart

__global__ void init_state() {
    int i = blockIdx.x * blockDim.x + threadIdx.x;
    if (i < 2 * NH * NB) g_ht[i] = 0.f;
    if (i < NBLK * 32)   g_bar[i] = 0;
}

// ---------------- embedding + input premul ---------------------------------
// out[t][col][b] = (E[tok(b,t)] @ W[0:D,col]) + bias[col]
// M = T*B rows (row = t*32+b), N = 1024, K = 128. 64x64 tiles, 256 threads.
__global__ void __launch_bounds__(256) embed_gemm(
    const int* __restrict__ tokens, int T, int which,
    const float* __restrict__ E, const float* __restrict__ W,
    const float* __restrict__ bias)
{
    float* out = which ? g_xz_dec : g_xz_enc;
    __shared__ float As[16][65];
    __shared__ float Bs[16][64];
    __shared__ int   tok[64];
    __shared__ float st[64][65];   // transpose staging for coalesced [t][col][b] store

    int tid  = threadIdx.x;
    int row0 = blockIdx.y * 64;
    int col0 = blockIdx.x * 64;

    if (tid < 64) {
        int row = row0 + tid;
        int b = row & 31, t = row >> 5;
        tok[tid] = tokens[b * T + t];
    }
    __syncthreads();

    int tx = tid & 15, ty = tid >> 4;
    float acc[4][4] = {};

    for (int k0 = 0; k0 < ND; k0 += 16) {
        #pragma unroll
        for (int i = 0; i < 4; i++) {
            int idx = tid + i * 256;
            int kk = idx >> 6, m = idx & 63;
            As[kk][m] = E[(long)tok[m] * ND + k0 + kk];
            Bs[kk][m] = W[(long)(k0 + kk) * NG4 + col0 + m];
        }
        __syncthreads();
        #pragma unroll
        for (int kk = 0; kk < 16; kk++) {
            float a[4], bfr[4];
            #pragma unroll
            for (int i = 0; i < 4; i++) a[i] = As[kk][ty * 4 + i];
            #pragma unroll
            for (int j = 0; j < 4; j++) bfr[j] = Bs[kk][tx * 4 + j];
            #pragma unroll
            for (int i = 0; i < 4; i++)
                #pragma unroll
                for (int j = 0; j < 4; j++)
                    acc[i][j] += a[i] * bfr[j];
        }
        __syncthreads();
    }
    #pragma unroll
    for (int i = 0; i < 4; i++)
        #pragma unroll
        for (int j = 0; j < 4; j++)
            st[ty * 4 + i][tx * 4 + j] = acc[i][j] + bias[col0 + tx * 4 + j];
    __syncthreads();

    // coalesced store: warp w handles columns w, w+8, ...; lanes = batch
    int w = tid >> 5, lane = tid & 31;
    int t0 = row0 >> 5;    // row0 is a multiple of 64 -> two t values per tile
    for (int cl = w; cl < 64; cl += 8) {
        long col = col0 + cl;
        out[((long)t0 * NG4 + col) * NB + lane]       = st[lane][cl];
        out[((long)(t0 + 1) * NG4 + col) * NB + lane] = st[32 + lane][cl];
    }
}

__device__ __forceinline__ float sigm(float x) { return 1.f / (1.f + expf(-x)); }

__device__ __forceinline__ int ld_acq(const int* p) {
    int v;
    asm volatile("ld.acquire.gpu.global.s32 %0, [%1];" : "=r"(v) : "l"(p));
    return v;
}
__device__ __forceinline__ void st_rel(int* p, int v) {
    asm volatile("st.release.gpu.global.s32 [%0], %1;" :: "l"(p), "r"(v) : "memory");
}

// ---------------- persistent LSTM recurrence --------------------------------
// 128 blocks, all co-resident; one software grid barrier per step.
// Block bk owns hidden units {2bk, 2bk+1} => 8 gate columns. Weights in smem.
// Warp w computes partial dots over k in [32w, 32w+32) for all 8 cols, lane=batch.
__global__ void __launch_bounds__(256, 1) lstm_persist(
    const float* __restrict__ W_enc, const float* __restrict__ W_dec,
    const int* __restrict__ len)
{
    __shared__ __align__(16) float2 wpen[128][8];  // enc weight pairs [kp][c]
    __shared__ __align__(16) float2 wpdc[128][8];  // dec weight pairs [kp][c]
    __shared__ float psum[8 * 256];                // [warp][c*32+b]

    int tid  = threadIdx.x;
    int bk   = blockIdx.x;
    int lane = tid & 31;
    int w    = tid >> 5;
    int u0   = bk * 2;

    // preload both weight slices: 8 cols x 256 k each, pair-interleaved on k
    for (int i = tid; i < 2048; i += 256) {
        int k = i >> 3, c = i & 7;
        int gcol = (c >> 1) * NH + u0 + (c & 1);
        float ve = W_enc[(long)(ND + k) * NG4 + gcol];
        float vd = W_dec[(long)(ND + k) * NG4 + gcol];
        if (k & 1) { wpen[k >> 1][c].y = ve; wpdc[k >> 1][c].y = vd; }
        else       { wpen[k >> 1][c].x = ve; wpdc[k >> 1][c].x = vd; }
    }

    // persistent per-(unit,batch) state in registers (threads 0..63)
    float creg = 0.f, hreg = 0.f;
    int ul = tid >> 5;          // 0/1 for tid<64
    int bb = tid & 31;
    int mylen = (tid < 64) ? len[bb] : 0;

    __syncthreads();

    for (int s = 0; s < NSTEPS; s++) {
        int p = s & 1;
        int is_enc = (s < NTX);
        int t = is_enc ? s : s - NTX;
        const float* xz = (is_enc ? g_xz_enc : g_xz_dec) + (long)t * NG4 * NB;

        // prefetch gate x-parts for finalize (off critical path)
        float x_i = 0.f, x_j = 0.f, x_f = 0.f, x_o = 0.f;
        if (tid < 64) {
            int u = u0 + ul;
            x_i = __ldg(&xz[((long)0 * NH + u) * NB + bb]);
            x_j = __ldg(&xz[((long)1 * NH + u) * NB + bb]);
            x_f = __ldg(&xz[((long)2 * NH + u) * NB + bb]);
            x_o = __ldg(&xz[((long)3 * NH + u) * NB + bb]);
        }

        // load h slice (bypass L1: written by other SMs last step)
        const float* hsrc = g_ht + (long)p * NH * NB;
        float hv[32];
        #pragma unroll
        for (int k = 0; k < 32; k++)
            hv[k] = __ldcg(hsrc + (w * 32 + k) * NB + lane);

        // packed-pair FMAs: acc2[c] += (h2k,h2k1) * (w2k,w2k1)
        unsigned long long acc2[8];
        #pragma unroll
        for (int c = 0; c < 8; c++) acc2[c] = 0ull;

        const ulonglong2* wrow = is_enc
            ? reinterpret_cast<const ulonglong2*>(&wpen[0][0])
            : reinterpret_cast<const ulonglong2*>(&wpdc[0][0]);

        #pragma unroll
        for (int kp = 0; kp < 16; kp++) {
            unsigned long long a2;
            asm("mov.b64 %0, {%1, %2};" : "=l"(a2)
                : "f"(hv[2 * kp]), "f"(hv[2 * kp + 1]));
            int gkp = w * 16 + kp;
            #pragma unroll
            for (int j = 0; j < 4; j++) {
                ulonglong2 q = wrow[gkp * 4 + j];
                asm("fma.rn.f32x2 %0, %1, %2, %3;"
                    : "=l"(acc2[2 * j]) : "l"(a2), "l"(q.x), "l"(acc2[2 * j]));
                asm("fma.rn.f32x2 %0, %1, %2, %3;"
                    : "=l"(acc2[2 * j + 1]) : "l"(a2), "l"(q.y), "l"(acc2[2 * j + 1]));
            }
        }
        #pragma unroll
        for (int c = 0; c < 8; c++) {
            float lo = __uint_as_float((unsigned)(acc2[c] & 0xffffffffull));
            float hi = __uint_as_float((unsigned)(acc2[c] >> 32));
            psum[w * 256 + c * 32 + lane] = lo + hi;
        }
        __syncthreads();

        // finalize: 64 threads, one (unit, batch) each
        if (tid < 64) {
            float zi = x_i, zj = x_j, zf = x_f, zo = x_o;
            #pragma unroll
            for (int ww = 0; ww < 8; ww++) {
                zi += psum[ww * 256 + (0 + ul) * 32 + bb];
                zj += psum[ww * 256 + (2 + ul) * 32 + bb];
                zf += psum[ww * 256 + (4 + ul) * 32 + bb];
                zo += psum[ww * 256 + (6 + ul) * 32 + bb];
            }
            float nc = creg * sigm(zf + 1.f) + sigm(zi) * tanhf(zj);
            float nh = tanhf(nc) * sigm(zo);
            if (is_enc && t >= mylen) { nc = creg; nh = hreg; }
            creg = nc; hreg = nh;
            int u = u0 + ul;
            g_ht[(long)(p ^ 1) * NH * NB + (long)u * NB + bb] = nh;
            if (!is_enc) g_hs[((long)t * NB + bb) * NH + u] = nh;
        }
        __syncthreads();

        // grid barrier (epoch = s+1)
        if (tid == 0) st_rel(&g_bar[bk * 32], s + 1);
        if (tid < NBLK) {
            while (ld_acq(&g_bar[tid * 32]) < s + 1) { }
        }
        __syncthreads();
    }
}

// ---------------- projection: logits[b][t][v] = hs[t][b][:] @ Wp[:, v] -----
// M=2048 (t*B+b), N=50000, K=256. 128x128 tile, kt=8, 8x8 micro, packed f32x2.
__global__ void __launch_bounds__(256) proj_gemm(
    const float* __restrict__ Wp, float* __restrict__ out)
{
    __shared__ float As[8][128];
    __shared__ float Bs[8][128];

    int tid  = threadIdx.x;
    int col0 = blockIdx.x * 128;
    int row0 = blockIdx.y * 128;
    int tx = tid & 15, ty = tid >> 4;

    unsigned long long acc2[4][8];
    #pragma unroll
    for (int i = 0; i < 4; i++)
        #pragma unroll
        for (int j = 0; j < 8; j++) acc2[i][j] = 0ull;

    int aRow = tid >> 1, aK = (tid & 1) * 4;
    int bK   = tid >> 5, bN = (tid & 31) * 4;

    for (int k0 = 0; k0 < NH; k0 += 8) {
        float4 a4 = *reinterpret_cast<const float4*>(
            &g_hs[(long)(row0 + aRow) * NH + k0 + aK]);
        As[aK + 0][aRow] = a4.x;
        As[aK + 1][aRow] = a4.y;
        As[aK + 2][aRow] = a4.z;
        As[aK + 3][aRow] = a4.w;

        int gn = col0 + bN;
        float4 b4 = make_float4(0.f, 0.f, 0.f, 0.f);
        if (gn < NV)
            b4 = *reinterpret_cast<const float4*>(&Wp[(long)(k0 + bK) * NV + gn]);
        *reinterpret_cast<float4*>(&Bs[bK][bN]) = b4;
        __syncthreads();

        #pragma unroll
        for (int kk = 0; kk < 8; kk++) {
            const ulonglong2* ap =
                reinterpret_cast<const ulonglong2*>(&As[kk][ty * 8]);
            ulonglong2 A01 = ap[0], A23 = ap[1];
            unsigned long long a[4] = {A01.x, A01.y, A23.x, A23.y};
            float4 blo = *reinterpret_cast<const float4*>(&Bs[kk][tx * 8]);
            float4 bhi = *reinterpret_cast<const float4*>(&Bs[kk][tx * 8 + 4]);
            float bf[8] = {blo.x, blo.y, blo.z, blo.w, bhi.x, bhi.y, bhi.z, bhi.w};
            #pragma unroll
            for (int j = 0; j < 8; j++) {
                unsigned long long bbp;
                asm("mov.b64 %0, {%1, %2};" : "=l"(bbp) : "f"(bf[j]), "f"(bf[j]));
                #pragma unroll
                for (int i = 0; i < 4; i++)
                    asm("fma.rn.f32x2 %0, %1, %2, %3;"
                        : "=l"(acc2[i][j])
                        : "l"(a[i]), "l"(bbp), "l"(acc2[i][j]));
            }
        }
        __syncthreads();
    }

    #pragma unroll
    for (int i2 = 0; i2 < 4; i2++) {
        int m0 = row0 + ty * 8 + i2 * 2;
        #pragma unroll
        for (int j = 0; j < 8; j++) {
            int n = col0 + tx * 8 + j;
            if (n < NV) {
                unsigned long long v = acc2[i2][j];
                float lo = __uint_as_float((unsigned)(v & 0xffffffffull));
                float hi = __uint_as_float((unsigned)(v >> 32));
                int m = m0, tt = m >> 5, bb = m & 31;
                out[(long)bb * NTY * NV + (long)tt * NV + n] = lo;
                m = m0 + 1; tt = m >> 5; bb = m & 31;
                out[(long)bb * NTY * NV + (long)tt * NV + n] = hi;
            }
        }
    }
}

// ---------------- launch ----------------------------------------------------
extern "C" void kernel_launch(void* const* d_in, const int* in_sizes, int n_in,
                              void* d_out, int out_size)
{
    const int*   enc_in = (const int*)d_in[0];
    const int*   dec_in = (const int*)d_in[1];
    const int*   len    = (const int*)d_in[2];
    const float* E      = (const float*)d_in[3];
    const float* W_enc  = (const float*)d_in[4];
    const float* b_enc  = (const float*)d_in[5];
    const float* W_dec  = (const float*)d_in[6];
    const float* b_dec  = (const float*)d_in[7];
    const float* W_proj = (const float*)d_in[8];
    float* out = (float*)d_out;

    init_state<<<64, 256>>>();

    // x-part of all gate pre-activations (bias folded in), layout [t][col][b]
    embed_gemm<<<dim3(16, (NTX * NB) / 64), 256>>>(enc_in, NTX, 0, E, W_enc, b_enc);
    embed_gemm<<<dim3(16, (NTY * NB) / 64), 256>>>(dec_in, NTY, 1, E, W_dec, b_dec);

    // whole recurrence in one persistent kernel
    lstm_persist<<<NBLK, 256>>>(W_enc, W_dec, len);

    // output projection
    proj_gemm<<<dim3((NV + 127) / 128, (NTY * NB) / 128), 256>>>(W_proj, out);
}

// round 4
// speedup vs baseline: 2.8074x; 1.8235x over previous
#include <cuda_runtime.h>
#include <cuda_bf16.h>
#include <math.h>
#include <stdint.h>

// Problem dims
#define NB   32
#define NTX  128
#define NTY  64
#define NV   50000
#define ND   128
#define NH   256
#define NG4  1024
#define NSTEPS (NTX + NTY)
#define NBLK 128

// Projection tiling
#define MT   128
#define NT   128
#define NMT  16                       // 2048 / 128 M-tiles
#define NNT  ((NV + NT - 1) / NT)     // 391 N-tiles
#define NGRP 9                        // 16*9 = 144 CTAs, single wave

// proj smem layout (bytes, from dynamic smem base)
#define APITCH    528                 // 264 bf16 per row (odd 16B multiple: conflict-free)
#define ASPLIT    (128 * APITCH)      // 67584 per split
#define B_OFF     (2 * ASPLIT)        // 135168
#define BPITCH    144                 // 72 bf16 per row
#define BSPLIT    (128 * BPITCH)      // 18432 per (buf,split)
#define PROJ_SMEM (B_OFF + 4 * BSPLIT)   // 208896

// ---------------- scratch (device globals) ----------------------------------
__device__ float g_xz_enc[NTX * NG4 * NB];
__device__ float g_xz_dec[NTY * NG4 * NB];
__device__ float g_ht[2 * NH * NB];
__device__ int   g_bar[NBLK * 32];
__device__ __align__(16) __nv_bfloat16 g_hsh[NTY * NB * NH];  // hs hi [m][k]
__device__ __align__(16) __nv_bfloat16 g_hsl[NTY * NB * NH];  // hs lo
__device__ __align__(16) __nv_bfloat16 g_wth[(long)NV * NH];  // W_proj^T hi [v][k]
__device__ __align__(16) __nv_bfloat16 g_wtl[(long)NV * NH];  // W_proj^T lo

// ---------------- helpers ----------------------------------------------------
__device__ __forceinline__ uint32_t smem_u32(const void* p) {
    uint32_t a;
    asm("{ .reg .u64 t; cvta.to.shared.u64 t, %1; cvt.u32.u64 %0, t; }"
        : "=r"(a) : "l"(p));
    return a;
}
__device__ __forceinline__ void ldsm4(uint32_t* r, uint32_t addr) {
    asm volatile("ldmatrix.sync.aligned.m8n8.x4.shared.b16 {%0,%1,%2,%3}, [%4];"
                 : "=r"(r[0]), "=r"(r[1]), "=r"(r[2]), "=r"(r[3]) : "r"(addr));
}
__device__ __forceinline__ void mma16816(float* c, const uint32_t* a,
                                         const uint32_t* b) {
    asm volatile(
        "mma.sync.aligned.m16n8k16.row.col.f32.bf16.bf16.f32 "
        "{%0,%1,%2,%3}, {%4,%5,%6,%7}, {%8,%9}, {%0,%1,%2,%3};"
        : "+f"(c[0]), "+f"(c[1]), "+f"(c[2]), "+f"(c[3])
        : "r"(a[0]), "r"(a[1]), "r"(a[2]), "r"(a[3]), "r"(b[0]), "r"(b[1]));
}
__device__ __forceinline__ void cp16(uint32_t dst, const void* src, int sz) {
    asm volatile("cp.async.cg.shared.global [%0], [%1], 16, %2;"
                 :: "r"(dst), "l"(src), "r"(sz));
}

__global__ void init_state() {
    int i = blockIdx.x * blockDim.x + threadIdx.x;
    if (i < 2 * NH * NB) g_ht[i] = 0.f;
    if (i < NBLK * 32)   g_bar[i] = 0;
}

// ---------------- W_proj transpose + bf16 hi/lo split ------------------------
__global__ void __launch_bounds__(256) wsplit(const float* __restrict__ W) {
    __shared__ float tile[32][33];
    int v0 = blockIdx.x * 32, k0 = blockIdx.y * 32;
    int tx = threadIdx.x & 31, ty = threadIdx.x >> 5;
    #pragma unroll
    for (int i = 0; i < 4; i++) {
        int k = k0 + ty + i * 8, v = v0 + tx;
        tile[ty + i * 8][tx] = (v < NV) ? W[(long)k * NV + v] : 0.f;
    }
    __syncthreads();
    #pragma unroll
    for (int i = 0; i < 4; i++) {
        int v = v0 + ty + i * 8;
        if (v < NV) {
            float x = tile[tx][ty + i * 8];
            __nv_bfloat16 h = __float2bfloat16(x);
            float r = x - __bfloat162float(h);
            g_wth[(long)v * NH + k0 + tx] = h;
            g_wtl[(long)v * NH + k0 + tx] = __float2bfloat16(r);
        }
    }
}

// ---------------- embedding + input premul ---------------------------------
__global__ void __launch_bounds__(256) embed_gemm(
    const int* __restrict__ tokens, int T, int which,
    const float* __restrict__ E, const float* __restrict__ W,
    const float* __restrict__ bias)
{
    float* out = which ? g_xz_dec : g_xz_enc;
    __shared__ float As[16][65];
    __shared__ float Bs[16][64];
    __shared__ int   tok[64];
    __shared__ float st[64][65];

    int tid  = threadIdx.x;
    int row0 = blockIdx.y * 64;
    int col0 = blockIdx.x * 64;

    if (tid < 64) {
        int row = row0 + tid;
        int b = row & 31, t = row >> 5;
        tok[tid] = tokens[b * T + t];
    }
    __syncthreads();

    int tx = tid & 15, ty = tid >> 4;
    float acc[4][4] = {};

    for (int k0 = 0; k0 < ND; k0 += 16) {
        #pragma unroll
        for (int i = 0; i < 4; i++) {
            int idx = tid + i * 256;
            int kk = idx >> 6, m = idx & 63;
            As[kk][m] = E[(long)tok[m] * ND + k0 + kk];
            Bs[kk][m] = W[(long)(k0 + kk) * NG4 + col0 + m];
        }
        __syncthreads();
        #pragma unroll
        for (int kk = 0; kk < 16; kk++) {
            float a[4], bfr[4];
            #pragma unroll
            for (int i = 0; i < 4; i++) a[i] = As[kk][ty * 4 + i];
            #pragma unroll
            for (int j = 0; j < 4; j++) bfr[j] = Bs[kk][tx * 4 + j];
            #pragma unroll
            for (int i = 0; i < 4; i++)
                #pragma unroll
                for (int j = 0; j < 4; j++)
                    acc[i][j] += a[i] * bfr[j];
        }
        __syncthreads();
    }
    #pragma unroll
    for (int i = 0; i < 4; i++)
        #pragma unroll
        for (int j = 0; j < 4; j++)
            st[ty * 4 + i][tx * 4 + j] = acc[i][j] + bias[col0 + tx * 4 + j];
    __syncthreads();

    int w = tid >> 5, lane = tid & 31;
    int t0 = row0 >> 5;
    for (int cl = w; cl < 64; cl += 8) {
        long col = col0 + cl;
        out[((long)t0 * NG4 + col) * NB + lane]       = st[lane][cl];
        out[((long)(t0 + 1) * NG4 + col) * NB + lane] = st[32 + lane][cl];
    }
}

__device__ __forceinline__ float sigm(float x) { return 1.f / (1.f + expf(-x)); }
__device__ __forceinline__ int ld_acq(const int* p) {
    int v; asm volatile("ld.acquire.gpu.global.s32 %0, [%1];" : "=r"(v) : "l"(p)); return v;
}
__device__ __forceinline__ void st_rel(int* p, int v) {
    asm volatile("st.release.gpu.global.s32 [%0], %1;" :: "l"(p), "r"(v) : "memory");
}

// ---------------- persistent LSTM recurrence --------------------------------
__global__ void __launch_bounds__(256, 1) lstm_persist(
    const float* __restrict__ W_enc, const float* __restrict__ W_dec,
    const int* __restrict__ len)
{
    __shared__ __align__(16) float2 wpen[128][8];
    __shared__ __align__(16) float2 wpdc[128][8];
    __shared__ float psum[8 * 256];

    int tid  = threadIdx.x;
    int bk   = blockIdx.x;
    int lane = tid & 31;
    int w    = tid >> 5;
    int u0   = bk * 2;

    for (int i = tid; i < 2048; i += 256) {
        int k = i >> 3, c = i & 7;
        int gcol = (c >> 1) * NH + u0 + (c & 1);
        float ve = W_enc[(long)(ND + k) * NG4 + gcol];
        float vd = W_dec[(long)(ND + k) * NG4 + gcol];
        if (k & 1) { wpen[k >> 1][c].y = ve; wpdc[k >> 1][c].y = vd; }
        else       { wpen[k >> 1][c].x = ve; wpdc[k >> 1][c].x = vd; }
    }

    float creg = 0.f, hreg = 0.f;
    int ul = tid >> 5;
    int bb = tid & 31;
    int mylen = (tid < 64) ? len[bb] : 0;

    __syncthreads();

    for (int s = 0; s < NSTEPS; s++) {
        int p = s & 1;
        int is_enc = (s < NTX);
        int t = is_enc ? s : s - NTX;
        const float* xz = (is_enc ? g_xz_enc : g_xz_dec) + (long)t * NG4 * NB;

        float x_i = 0.f, x_j = 0.f, x_f = 0.f, x_o = 0.f;
        if (tid < 64) {
            int u = u0 + ul;
            x_i = __ldg(&xz[((long)0 * NH + u) * NB + bb]);
            x_j = __ldg(&xz[((long)1 * NH + u) * NB + bb]);
            x_f = __ldg(&xz[((long)2 * NH + u) * NB + bb]);
            x_o = __ldg(&xz[((long)3 * NH + u) * NB + bb]);
        }

        const float* hsrc = g_ht + (long)p * NH * NB;
        float hv[32];
        #pragma unroll
        for (int k = 0; k < 32; k++)
            hv[k] = __ldcg(hsrc + (w * 32 + k) * NB + lane);

        unsigned long long acc2[8];
        #pragma unroll
        for (int c = 0; c < 8; c++) acc2[c] = 0ull;

        const ulonglong2* wrow = is_enc
            ? reinterpret_cast<const ulonglong2*>(&wpen[0][0])
            : reinterpret_cast<const ulonglong2*>(&wpdc[0][0]);

        #pragma unroll
        for (int kp = 0; kp < 16; kp++) {
            unsigned long long a2;
            asm("mov.b64 %0, {%1, %2};" : "=l"(a2)
                : "f"(hv[2 * kp]), "f"(hv[2 * kp + 1]));
            int gkp = w * 16 + kp;
            #pragma unroll
            for (int j = 0; j < 4; j++) {
                ulonglong2 q = wrow[gkp * 4 + j];
                asm("fma.rn.f32x2 %0, %1, %2, %3;"
                    : "=l"(acc2[2 * j]) : "l"(a2), "l"(q.x), "l"(acc2[2 * j]));
                asm("fma.rn.f32x2 %0, %1, %2, %3;"
                    : "=l"(acc2[2 * j + 1]) : "l"(a2), "l"(q.y), "l"(acc2[2 * j + 1]));
            }
        }
        #pragma unroll
        for (int c = 0; c < 8; c++) {
            float lo = __uint_as_float((unsigned)(acc2[c] & 0xffffffffull));
            float hi = __uint_as_float((unsigned)(acc2[c] >> 32));
            psum[w * 256 + c * 32 + lane] = lo + hi;
        }
        __syncthreads();

        if (tid < 64) {
            float zi = x_i, zj = x_j, zf = x_f, zo = x_o;
            #pragma unroll
            for (int ww = 0; ww < 8; ww++) {
                zi += psum[ww * 256 + (0 + ul) * 32 + bb];
                zj += psum[ww * 256 + (2 + ul) * 32 + bb];
                zf += psum[ww * 256 + (4 + ul) * 32 + bb];
                zo += psum[ww * 256 + (6 + ul) * 32 + bb];
            }
            float nc = creg * sigm(zf + 1.f) + sigm(zi) * tanhf(zj);
            float nh = tanhf(nc) * sigm(zo);
            if (is_enc && t >= mylen) { nc = creg; nh = hreg; }
            creg = nc; hreg = nh;
            int u = u0 + ul;
            g_ht[(long)(p ^ 1) * NH * NB + (long)u * NB + bb] = nh;
            if (!is_enc) {
                __nv_bfloat16 hh = __float2bfloat16(nh);
                float rr = nh - __bfloat162float(hh);
                long mrow = (long)t * NB + bb;
                g_hsh[mrow * NH + u] = hh;
                g_hsl[mrow * NH + u] = __float2bfloat16(rr);
            }
        }
        __syncthreads();

        if (tid == 0) st_rel(&g_bar[bk * 32], s + 1);
        if (tid < NBLK) {
            while (ld_acq(&g_bar[tid * 32]) < s + 1) { }
        }
        __syncthreads();
    }
}

// ---------------- projection via mma.sync bf16 3-term split -----------------
// Persistent CTA = (M-tile, n-group). A (hi+lo) resident in SMEM (pitch 528B);
// B streamed as 64-k chunks, cp.async double-buffered (pitch 144B).
extern __shared__ __align__(16) char proj_sm[];
__global__ void __launch_bounds__(256, 1) proj_mma(float* __restrict__ out)
{
    uint32_t sbase = smem_u32(proj_sm);
    int tid  = threadIdx.x;
    int lane = tid & 31;
    int wid  = tid >> 5;
    int wm   = wid >> 2;        // 0..1 -> M quadrant (64 rows)
    int wn   = wid & 3;         // 0..3 -> N quadrant (32 cols)
    int row0 = blockIdx.x * MT;
    int ng   = blockIdx.y;

    // ---- load resident A tile (hi+lo), pitch 528 B ----
    for (int i = tid; i < 8192; i += 256) {
        int s = i >> 12, w = i & 4095, row = w >> 5, kseg = w & 31;
        const __nv_bfloat16* src = s ? g_hsl : g_hsh;
        uint4 v = *reinterpret_cast<const uint4*>(
            src + (long)(row0 + row) * NH + kseg * 8);
        *reinterpret_cast<uint4*>(proj_sm + s * ASPLIT + row * APITCH + kseg * 16) = v;
    }
    __syncthreads();

    // ldmatrix address bases (per-thread)
    // A: threads 0-15 -> rows 0-15 @klo, threads 16-31 -> rows 0-15 @khi
    uint32_t aBase = sbase + (wm * 64 + (lane & 15)) * APITCH + ((lane >> 4) * 8) * 2;
    // B: t0-7: n+t,klo | t8-15: n+t-8,khi | t16-23: n+8+..,klo | t24-31: n+8+..,khi
    uint32_t bBase = sbase + B_OFF
                   + (wn * 32 + (lane & 7) + ((lane >> 4) << 3)) * BPITCH
                   + (((lane >> 3) & 1) * 8) * 2;

    for (int nt = ng; nt < NNT; nt += NGRP) {
        int col0 = nt * NT;
        float acc[4][4][4];
        #pragma unroll
        for (int a = 0; a < 4; a++)
            #pragma unroll
            for (int b = 0; b < 4; b++)
                #pragma unroll
                for (int c = 0; c < 4; c++) acc[a][b][c] = 0.f;

        // prefetch chunk 0 into buf 0
        #pragma unroll 1
        for (int pc = 0; pc < 1; pc++) {
            for (int i = tid; i < 2048; i += 256) {
                int s = i >> 10, w = i & 1023, v = w >> 3, seg = w & 7;
                int gv = col0 + v;
                int cgv = gv < NV ? gv : NV - 1;
                const __nv_bfloat16* src =
                    (s ? g_wtl : g_wth) + (long)cgv * NH + seg * 8;
                uint32_t dst = sbase + B_OFF + s * BSPLIT + v * BPITCH + seg * 16;
                cp16(dst, src, gv < NV ? 16 : 0);
            }
            asm volatile("cp.async.commit_group;" ::: "memory");
        }

        #pragma unroll 1
        for (int c = 0; c < 4; c++) {
            if (c < 3) {
                int nb = (c + 1) & 1;
                for (int i = tid; i < 2048; i += 256) {
                    int s = i >> 10, w = i & 1023, v = w >> 3, seg = w & 7;
                    int gv = col0 + v;
                    int cgv = gv < NV ? gv : NV - 1;
                    const __nv_bfloat16* src =
                        (s ? g_wtl : g_wth) + (long)cgv * NH + (c + 1) * 64 + seg * 8;
                    uint32_t dst = sbase + B_OFF + (nb * 2 + s) * BSPLIT
                                 + v * BPITCH + seg * 16;
                    cp16(dst, src, gv < NV ? 16 : 0);
                }
                asm volatile("cp.async.commit_group;" ::: "memory");
                asm volatile("cp.async.wait_group 1;" ::: "memory");
            } else {
                asm volatile("cp.async.wait_group 0;" ::: "memory");
            }
            __syncthreads();

            int buf = c & 1;
            uint32_t bBufH = bBase + (buf * 2 + 0) * BSPLIT;
            uint32_t bBufL = bBase + (buf * 2 + 1) * BSPLIT;

            #pragma unroll
            for (int kk = 0; kk < 4; kk++) {
                int kg = c * 64 + kk * 16;
                uint32_t ah[4][4], al[4][4];
                #pragma unroll
                for (int mt = 0; mt < 4; mt++) {
                    ldsm4(ah[mt], aBase + mt * (16 * APITCH) + kg * 2);
                    ldsm4(al[mt], aBase + ASPLIT + mt * (16 * APITCH) + kg * 2);
                }
                uint32_t bh[2][4], bl[2][4];
                int kl = kk * 16;
                #pragma unroll
                for (int l = 0; l < 2; l++) {
                    ldsm4(bh[l], bBufH + l * (16 * BPITCH) + kl * 2);
                    ldsm4(bl[l], bBufL + l * (16 * BPITCH) + kl * 2);
                }
                #pragma unroll
                for (int mt = 0; mt < 4; mt++) {
                    #pragma unroll
                    for (int ntl = 0; ntl < 4; ntl++) {
                        int l = ntl >> 1, p = (ntl & 1) * 2;
                        uint32_t bhf[2] = {bh[l][p], bh[l][p + 1]};
                        uint32_t blf[2] = {bl[l][p], bl[l][p + 1]};
                        mma16816(acc[mt][ntl], ah[mt], bhf);
                        mma16816(acc[mt][ntl], ah[mt], blf);
                        mma16816(acc[mt][ntl], al[mt], bhf);
                    }
                }
            }
            __syncthreads();
        }

        // ---- epilogue: direct global stores ----
        #pragma unroll
        for (int mt = 0; mt < 4; mt++) {
            int r0 = row0 + wm * 64 + mt * 16 + (lane >> 2);
            int r1 = r0 + 8;
            int tt0 = r0 >> 5, bb0 = r0 & 31;
            int tt1 = r1 >> 5, bb1 = r1 & 31;
            float* o0 = out + (long)bb0 * NTY * NV + (long)tt0 * NV;
            float* o1 = out + (long)bb1 * NTY * NV + (long)tt1 * NV;
            #pragma unroll
            for (int ntl = 0; ntl < 4; ntl++) {
                int cc = col0 + wn * 32 + ntl * 8 + 2 * (lane & 3);
                if (cc < NV) {
                    float2 v0 = make_float2(acc[mt][ntl][0], acc[mt][ntl][1]);
                    float2 v1 = make_float2(acc[mt][ntl][2], acc[mt][ntl][3]);
                    *reinterpret_cast<float2*>(o0 + cc) = v0;
                    *reinterpret_cast<float2*>(o1 + cc) = v1;
                }
            }
        }
    }
}

// ---------------- launch ----------------------------------------------------
extern "C" void kernel_launch(void* const* d_in, const int* in_sizes, int n_in,
                              void* d_out, int out_size)
{
    const int*   enc_in = (const int*)d_in[0];
    const int*   dec_in = (const int*)d_in[1];
    const int*   len    = (const int*)d_in[2];
    const float* E      = (const float*)d_in[3];
    const float* W_enc  = (const float*)d_in[4];
    const float* b_enc  = (const float*)d_in[5];
    const float* W_dec  = (const float*)d_in[6];
    const float* b_dec  = (const float*)d_in[7];
    const float* W_proj = (const float*)d_in[8];
    float* out = (float*)d_out;

    cudaFuncSetAttribute(proj_mma, cudaFuncAttributeMaxDynamicSharedMemorySize,
                         PROJ_SMEM);

    init_state<<<64, 256>>>();

    wsplit<<<dim3((NV + 31) / 32, 8), 256>>>(W_proj);

    embed_gemm<<<dim3(16, (NTX * NB) / 64), 256>>>(enc_in, NTX, 0, E, W_enc, b_enc);
    embed_gemm<<<dim3(16, (NTY * NB) / 64), 256>>>(dec_in, NTY, 1, E, W_dec, b_dec);

    lstm_persist<<<NBLK, 256>>>(W_enc, W_dec, len);

    proj_mma<<<dim3(NMT, NGRP), 256, PROJ_SMEM>>>(out);
}